// round 3
// baseline (speedup 1.0000x reference)
#include <cuda_runtime.h>
#include <cuda_bf16.h>

// ChannelPolyLayer: out[b,o,x,y] = sum_c coeffs[b,o,c] * prod_v img[b,v,x,y]^powers[c,v]
// DEGREE=3, NUM_VARS=3, NUM_OUT=3, NUM_COEFFS=20, BATCH=16, H=W=512.
//
// Monomial order from _generate_powers(3,3):
//  0:1  1:v0  2:v1  3:v2  4:v0^2  5:v0v1  6:v0v2  7:v1^2  8:v1v2  9:v2^2
// 10:v0^3 11:v0^2v1 12:v0^2v2 13:v0v1^2 14:v0v1v2 15:v0v2^2
// 16:v1^3 17:v1^2v2 18:v1v2^2 19:v2^3
//
// Nested Horner (19 FMAs/output/pixel), evaluated 2 pixels at a time with
// packed fma.rn.f32x2 (sm_103a FFMA2). A float4 of adjacent pixels is
// bit-identical to two f32x2 packs, so data needs no pack/unpack movs;
// only the block-uniform coefficients are splatted to {c,c} pairs in shared.

#define HW_PIX (512 * 512)
#define HW4 (HW_PIX / 4)
#define NBATCH 16
#define NCOEF 20

typedef unsigned long long ull;

__device__ __forceinline__ ull ffma2(ull a, ull b, ull c) {
    ull d;
    asm("fma.rn.f32x2 %0, %1, %2, %3;" : "=l"(d) : "l"(a), "l"(b), "l"(c));
    return d;
}

// Horner over a packed pair of pixels. c[] are {coeff,coeff} splat pairs.
__device__ __forceinline__ ull horner2(ull v0, ull v1, ull v2,
                                       const ull* __restrict__ c) {
    // C0(v1,v2) = c0 + c2 v1 + c7 v1^2 + c16 v1^3
    //           + v2*(c3 + c8 v1 + c17 v1^2)
    //           + v2^2*(c9 + c18 v1) + c19 v2^3
    ull pA = ffma2(c[16], v1, c[7]);
    pA = ffma2(v1, pA, c[2]);
    pA = ffma2(v1, pA, c[0]);
    ull pB = ffma2(c[17], v1, c[8]);
    pB = ffma2(v1, pB, c[3]);
    ull pC = ffma2(c[18], v1, c[9]);
    ull C0 = ffma2(c[19], v2, pC);
    C0 = ffma2(C0, v2, pB);
    C0 = ffma2(C0, v2, pA);
    // C1(v1,v2)
    ull qA = ffma2(c[13], v1, c[5]);
    qA = ffma2(v1, qA, c[1]);
    ull qB = ffma2(c[14], v1, c[6]);
    ull C1 = ffma2(c[15], v2, qB);
    C1 = ffma2(C1, v2, qA);
    // C2(v1,v2)
    ull C2 = ffma2(c[11], v1, c[4]);
    C2 = ffma2(c[12], v2, C2);
    // Horner in v0
    ull r = ffma2(c[10], v0, C2);
    r = ffma2(r, v0, C1);
    r = ffma2(r, v0, C0);
    return r;
}

__global__ __launch_bounds__(256, 4) void channel_poly_kernel(
    const float* __restrict__ img,     // (B, 3, H, W)
    const float* __restrict__ coeffs,  // (B, 3, 20)
    float* __restrict__ out)           // (B, 3, H, W)
{
    __shared__ ull sc2[3 * NCOEF];
    const int b = blockIdx.y;
    const int t = threadIdx.x;
    if (t < 3 * NCOEF) {
        ull u = (ull)__float_as_uint(coeffs[b * (3 * NCOEF) + t]);
        sc2[t] = u | (u << 32);  // splat {c, c}
    }
    __syncthreads();

    const int i = blockIdx.x * blockDim.x + t;  // float4 (= f32x2 pair) index in plane

    const ulonglong2* __restrict__ in0 =
        reinterpret_cast<const ulonglong2*>(img + (size_t)b * 3 * HW_PIX);
    const ulonglong2 x0 = in0[i];              // channel 0, pixels {p0,p1},{p2,p3}
    const ulonglong2 x1 = in0[i + HW4];        // channel 1
    const ulonglong2 x2 = in0[i + 2 * HW4];    // channel 2

    ulonglong2* __restrict__ o =
        reinterpret_cast<ulonglong2*>(out + (size_t)b * 3 * HW_PIX);

#pragma unroll 1
    for (int oc = 0; oc < 3; oc++) {
        const ull* __restrict__ c = sc2 + oc * NCOEF;
        ulonglong2 r;
        r.x = horner2(x0.x, x1.x, x2.x, c);
        r.y = horner2(x0.y, x1.y, x2.y, c);
        o[i + oc * HW4] = r;
    }
}

extern "C" void kernel_launch(void* const* d_in, const int* in_sizes, int n_in,
                              void* d_out, int out_size) {
    const float* img = (const float*)d_in[0];     // (16,3,512,512)
    const float* coeffs = (const float*)d_in[1];  // (16,3,20)
    float* out = (float*)d_out;

    dim3 grid(HW4 / 256, NBATCH, 1);
    channel_poly_kernel<<<grid, 256>>>(img, coeffs, out);
}

// round 4
// speedup vs baseline: 1.0845x; 1.0845x over previous
#include <cuda_runtime.h>
#include <cuda_bf16.h>

// ChannelPolyLayer: out[b,o,x,y] = sum_c coeffs[b,o,c] * prod_v img[b,v,x,y]^powers[c,v]
// DEGREE=3, NUM_VARS=3, NUM_OUT=3, NUM_COEFFS=20, BATCH=16, H=W=512.
//
// Monomial order from _generate_powers(3,3):
//  0:1  1:v0  2:v1  3:v2  4:v0^2  5:v0v1  6:v0v2  7:v1^2  8:v1v2  9:v2^2
// 10:v0^3 11:v0^2v1 12:v0^2v2 13:v0v1^2 14:v0v1v2 15:v0v2^2
// 16:v1^3 17:v1^2v2 18:v1v2^2 19:v2^3
//
// Nested Horner (19 packed FMAs/output/2-pixels) with fma.rn.f32x2.
// R4: 2 float4 items per thread, all 6 LDG.128 front-batched to raise
// per-warp memory-level parallelism (latency-bound fix).

#define HW_PIX (512 * 512)
#define HW4 (HW_PIX / 4)
#define NBATCH 16
#define NCOEF 20

typedef unsigned long long ull;

__device__ __forceinline__ ull ffma2(ull a, ull b, ull c) {
    ull d;
    asm("fma.rn.f32x2 %0, %1, %2, %3;" : "=l"(d) : "l"(a), "l"(b), "l"(c));
    return d;
}

// Horner over a packed pair of pixels. c[] are {coeff,coeff} splat pairs.
__device__ __forceinline__ ull horner2(ull v0, ull v1, ull v2,
                                       const ull* __restrict__ c) {
    ull pA = ffma2(c[16], v1, c[7]);
    pA = ffma2(v1, pA, c[2]);
    pA = ffma2(v1, pA, c[0]);
    ull pB = ffma2(c[17], v1, c[8]);
    pB = ffma2(v1, pB, c[3]);
    ull pC = ffma2(c[18], v1, c[9]);
    ull C0 = ffma2(c[19], v2, pC);
    C0 = ffma2(C0, v2, pB);
    C0 = ffma2(C0, v2, pA);
    ull qA = ffma2(c[13], v1, c[5]);
    qA = ffma2(v1, qA, c[1]);
    ull qB = ffma2(c[14], v1, c[6]);
    ull C1 = ffma2(c[15], v2, qB);
    C1 = ffma2(C1, v2, qA);
    ull C2 = ffma2(c[11], v1, c[4]);
    C2 = ffma2(c[12], v2, C2);
    ull r = ffma2(c[10], v0, C2);
    r = ffma2(r, v0, C1);
    r = ffma2(r, v0, C0);
    return r;
}

__global__ __launch_bounds__(256, 3) void channel_poly_kernel(
    const float* __restrict__ img,     // (B, 3, H, W)
    const float* __restrict__ coeffs,  // (B, 3, 20)
    float* __restrict__ out)           // (B, 3, H, W)
{
    __shared__ ull sc2[3 * NCOEF];
    const int b = blockIdx.y;
    const int t = threadIdx.x;
    if (t < 3 * NCOEF) {
        ull u = (ull)__float_as_uint(coeffs[b * (3 * NCOEF) + t]);
        sc2[t] = u | (u << 32);  // splat {c, c}
    }
    __syncthreads();

    // Each block covers 512 float4s: item a at base+t, item b at base+256+t.
    const int ia = blockIdx.x * 512 + t;
    const int ib = ia + 256;

    const ulonglong2* __restrict__ in0 =
        reinterpret_cast<const ulonglong2*>(img + (size_t)b * 3 * HW_PIX);

    // Front-batch all 6 LDG.128 (maximize outstanding loads per warp).
    const ulonglong2 a0 = in0[ia];
    const ulonglong2 a1 = in0[ia + HW4];
    const ulonglong2 a2 = in0[ia + 2 * HW4];
    const ulonglong2 b0 = in0[ib];
    const ulonglong2 b1 = in0[ib + HW4];
    const ulonglong2 b2 = in0[ib + 2 * HW4];

    ulonglong2* __restrict__ o =
        reinterpret_cast<ulonglong2*>(out + (size_t)b * 3 * HW_PIX);

#pragma unroll 1
    for (int oc = 0; oc < 3; oc++) {
        const ull* __restrict__ c = sc2 + oc * NCOEF;
        ulonglong2 ra, rb;
        ra.x = horner2(a0.x, a1.x, a2.x, c);
        ra.y = horner2(a0.y, a1.y, a2.y, c);
        rb.x = horner2(b0.x, b1.x, b2.x, c);
        rb.y = horner2(b0.y, b1.y, b2.y, c);
        o[ia + oc * HW4] = ra;
        o[ib + oc * HW4] = rb;
    }
}

extern "C" void kernel_launch(void* const* d_in, const int* in_sizes, int n_in,
                              void* d_out, int out_size) {
    const float* img = (const float*)d_in[0];     // (16,3,512,512)
    const float* coeffs = (const float*)d_in[1];  // (16,3,20)
    float* out = (float*)d_out;

    dim3 grid(HW4 / 512, NBATCH, 1);   // 128 x 16
    channel_poly_kernel<<<grid, 256>>>(img, coeffs, out);
}